// round 2
// baseline (speedup 1.0000x reference)
#include <cuda_runtime.h>
#include <cuda_bf16.h>
#include <stdint.h>

// ---------------------------------------------------------------------------
// Problem constants
// ---------------------------------------------------------------------------
#define T_TOK   4096      // B*S = 4*1024 tokens
#define D_MODEL 1024
#define N_SLOT  4096
#define MAX_K   32
#define MIN_K   8

// ---------------------------------------------------------------------------
// Device-global scratch (allowed; no runtime allocation)
// ---------------------------------------------------------------------------
__device__ float g_logits[(size_t)T_TOK * N_SLOT];   // 64 MB
__device__ float g_max[T_TOK];
__device__ float g_invd[T_TOK];                       // 1/sumexp per token
__device__ float g_colsum[N_SLOT];
__device__ int   g_counts[N_SLOT];
__device__ int   g_idxbuf[T_TOK * MAX_K];
__device__ float g_wbuf[T_TOK * MAX_K];

// ---------------------------------------------------------------------------
// Fast exp (FFMA-only, ~1e-6 rel err) — avoids MUFU throughput wall for the
// ~33M exp evaluations (softmax denom + column means).
// ---------------------------------------------------------------------------
__device__ __forceinline__ float fexp(float x) {
    float y = x * 1.4426950408889634f;          // log2(e)
    y = fmaxf(y, -126.0f);
    float fi = floorf(y);
    float f  = y - fi;                           // f in [0,1)
    // 2^f = exp(f*ln2): Taylor, coeffs ln2^k/k!
    float p = 1.52527338040e-5f;
    p = fmaf(p, f, 1.54035303933e-4f);
    p = fmaf(p, f, 1.33335581464e-3f);
    p = fmaf(p, f, 9.61812910763e-3f);
    p = fmaf(p, f, 5.55041086648e-2f);
    p = fmaf(p, f, 2.40226506959e-1f);
    p = fmaf(p, f, 6.93147180560e-1f);
    p = fmaf(p, f, 1.0f);
    int e = (int)fi;
    return __int_as_float((e + 127) << 23) * p;
}

// monotone float -> uint key (larger float => larger key)
__device__ __forceinline__ unsigned int mono(float f) {
    unsigned int u = __float_as_uint(f);
    return (u & 0x80000000u) ? ~u : (u | 0x80000000u);
}

// ---------------------------------------------------------------------------
// K0: zero accumulators (must run every replay — graph replays N times)
// ---------------------------------------------------------------------------
__global__ void k_zero() {
    int i = blockIdx.x * 256 + threadIdx.x;
    if (i < N_SLOT) { g_colsum[i] = 0.0f; g_counts[i] = 0; }
}

// ---------------------------------------------------------------------------
// K1: logits[T][N] = x[T][D] @ W[D][N]   (fp32 sgemm, 128x128x16 tiles)
// ---------------------------------------------------------------------------
__global__ __launch_bounds__(256) void k_gemm(const float* __restrict__ A,
                                              const float* __restrict__ B) {
    __shared__ float As[16][128];
    __shared__ float Bs[16][128];
    int tid = threadIdx.x;
    int bm = blockIdx.y * 128;
    int bn = blockIdx.x * 128;
    int tm = (tid / 16) * 8;
    int tn = (tid % 16) * 8;
    float acc[8][8];
#pragma unroll
    for (int i = 0; i < 8; i++)
#pragma unroll
        for (int j = 0; j < 8; j++) acc[i][j] = 0.0f;

    for (int k0 = 0; k0 < D_MODEL; k0 += 16) {
        // load A tile 128x16 (transposed into As[k][m])
#pragma unroll
        for (int i = 0; i < 2; i++) {
            int v = tid + i * 256;            // float4 id in [0,512)
            int row = v >> 2;                 // 0..127
            int c4 = (v & 3) * 4;             // 0,4,8,12
            float4 a = *reinterpret_cast<const float4*>(
                &A[(size_t)(bm + row) * D_MODEL + k0 + c4]);
            As[c4 + 0][row] = a.x; As[c4 + 1][row] = a.y;
            As[c4 + 2][row] = a.z; As[c4 + 3][row] = a.w;
        }
        // load B tile 16x128
#pragma unroll
        for (int i = 0; i < 2; i++) {
            int v = tid + i * 256;
            int row = v >> 5;                 // 0..15
            int c4 = (v & 31) * 4;
            *reinterpret_cast<float4*>(&Bs[row][c4]) =
                *reinterpret_cast<const float4*>(
                    &B[(size_t)(k0 + row) * N_SLOT + bn + c4]);
        }
        __syncthreads();
#pragma unroll
        for (int k = 0; k < 16; k++) {
            float ar[8], br[8];
#pragma unroll
            for (int i = 0; i < 8; i++) ar[i] = As[k][tm + i];
#pragma unroll
            for (int j = 0; j < 8; j++) br[j] = Bs[k][tn + j];
#pragma unroll
            for (int i = 0; i < 8; i++)
#pragma unroll
                for (int j = 0; j < 8; j++)
                    acc[i][j] = fmaf(ar[i], br[j], acc[i][j]);
        }
        __syncthreads();
    }
#pragma unroll
    for (int i = 0; i < 8; i++) {
        float* crow = &g_logits[(size_t)(bm + tm + i) * N_SLOT + bn + tn];
        *reinterpret_cast<float4*>(crow) =
            make_float4(acc[i][0], acc[i][1], acc[i][2], acc[i][3]);
        *reinterpret_cast<float4*>(crow + 4) =
            make_float4(acc[i][4], acc[i][5], acc[i][6], acc[i][7]);
    }
}

// ---------------------------------------------------------------------------
// K2: per-token softmax stats + exact top-32 (radix select + warp bitonic),
//     keep mask, weights, scatter counts.
// ---------------------------------------------------------------------------
__global__ __launch_bounds__(256) void k_route() {
    int t = blockIdx.x;
    int tid = threadIdx.x;
    const float* row = g_logits + (size_t)t * N_SLOT;

    __shared__ float sv[N_SLOT];
    __shared__ unsigned int hist[256];
    __shared__ float red[8];
    __shared__ unsigned int s_prefix;
    __shared__ int s_want;
    __shared__ int s_cnt, s_eqcnt;
    __shared__ int sel[32];
    __shared__ int eqlist[64];
    __shared__ float s_max, s_sum;

    // load row + local max
    float lmax = -3.4e38f;
    float vals[16];
#pragma unroll
    for (int j = 0; j < 16; j++) {
        int i = tid + j * 256;
        float v = row[i];
        sv[i] = v;
        vals[j] = v;
        lmax = fmaxf(lmax, v);
    }
    // block max
#pragma unroll
    for (int o = 16; o; o >>= 1) lmax = fmaxf(lmax, __shfl_xor_sync(~0u, lmax, o));
    if ((tid & 31) == 0) red[tid >> 5] = lmax;
    __syncthreads();
    if (tid == 0) {
        float m = red[0];
#pragma unroll
        for (int w = 1; w < 8; w++) m = fmaxf(m, red[w]);
        s_max = m;
    }
    __syncthreads();
    float m = s_max;

    // block sumexp
    float lsum = 0.0f;
#pragma unroll
    for (int j = 0; j < 16; j++) lsum += fexp(vals[j] - m);
#pragma unroll
    for (int o = 16; o; o >>= 1) lsum += __shfl_xor_sync(~0u, lsum, o);
    if ((tid & 31) == 0) red[tid >> 5] = lsum;
    __syncthreads();
    if (tid == 0) {
        float s = 0.0f;
#pragma unroll
        for (int w = 0; w < 8; w++) s += red[w];
        s_sum = s;
    }
    __syncthreads();

    // ---- radix select for 32nd largest key ----
    unsigned int prefmask = 0u, prefix = 0u;
    int want = 32;
    for (int shift = 24; shift >= 0; shift -= 8) {
        hist[tid] = 0u;
        __syncthreads();
#pragma unroll
        for (int j = 0; j < 16; j++) {
            unsigned int kk = mono(vals[j]);
            if ((kk & prefmask) == prefix)
                atomicAdd(&hist[(kk >> shift) & 255u], 1u);
        }
        __syncthreads();
        if (tid == 0) {
            int cum = 0, b = 255;
            for (; b >= 0; b--) { cum += (int)hist[b]; if (cum >= want) break; }
            s_prefix = prefix | ((unsigned int)b << shift);
            s_want = want - (cum - (int)hist[b]);
        }
        __syncthreads();
        prefix = s_prefix;
        want = s_want;
        prefmask |= 0xFFu << shift;
        __syncthreads();
    }

    // ---- compaction ----
    if (tid == 0) { s_cnt = 0; s_eqcnt = 0; }
    __syncthreads();
#pragma unroll
    for (int j = 0; j < 16; j++) {
        int i = tid + j * 256;
        unsigned int kk = mono(vals[j]);
        if (kk > prefix) {
            int p = atomicAdd(&s_cnt, 1);
            if (p < 32) sel[p] = i;
        } else if (kk == prefix) {
            int p = atomicAdd(&s_eqcnt, 1);
            if (p < 64) eqlist[p] = i;
        }
    }
    __syncthreads();
    if (tid == 0) {
        // ties: lowest indices first (jax tie-break)
        int n = s_eqcnt < 64 ? s_eqcnt : 64;
        for (int a = 1; a < n; a++) {
            int key = eqlist[a]; int b = a - 1;
            while (b >= 0 && eqlist[b] > key) { eqlist[b + 1] = eqlist[b]; b--; }
            eqlist[b + 1] = key;
        }
        int base = s_cnt;
        for (int r = 0; r < want && r < n && base + r < 32; r++)
            sel[base + r] = eqlist[r];
    }
    __syncthreads();

    // ---- warp 0: bitonic sort 32 selected (value desc, index asc) ----
    if (tid < 32) {
        int idx = sel[tid];
        float val = sv[idx];
        unsigned long long key =
            ((unsigned long long)mono(val) << 32) |
            (unsigned long long)(0xFFFFFFFFu - (unsigned int)idx);
#pragma unroll
        for (int k = 2; k <= 32; k <<= 1) {
#pragma unroll
            for (int j = k >> 1; j > 0; j >>= 1) {
                unsigned long long o = __shfl_xor_sync(0xFFFFFFFFu, key, j);
                bool up = ((tid & k) == 0);
                bool takeMin = (((tid & j) == 0) == up);
                unsigned long long mn = key < o ? key : o;
                unsigned long long mx = key < o ? o : key;
                key = takeMin ? mn : mx;
            }
        }
        int rank = 31 - tid;  // ascending sort -> rank 0 at lane 31
        unsigned int myidx = 0xFFFFFFFFu - (unsigned int)(key & 0xFFFFFFFFu);
        float v = sv[myidx];
        float prob = fexp(v - s_max) * (1.0f / s_sum);
        bool keep = (rank < MIN_K) || (prob > (1.0f / (float)N_SLOT));
        float masked = keep ? prob : 0.0f;
        float ws = masked;
#pragma unroll
        for (int o = 16; o; o >>= 1) ws += __shfl_xor_sync(~0u, ws, o);
        float w = masked / (ws + 1e-9f);
        g_idxbuf[t * MAX_K + rank] = (int)myidx;
        g_wbuf[t * MAX_K + rank] = w;
        if (keep) atomicAdd(&g_counts[myidx], 1);
        if (tid == 0) { g_max[t] = s_max; g_invd[t] = 1.0f / s_sum; }
    }
}

// ---------------------------------------------------------------------------
// K3: column sums of softmax probs (for mean_probs / aux loss)
//     grid (N/256, 8); each block: 256 cols x 512 tokens
// ---------------------------------------------------------------------------
__global__ __launch_bounds__(256) void k_colsum() {
    __shared__ float sm[32 * 256];
    __shared__ float smax[32], sinv[32];
    int tid = threadIdx.x;
    int cb = blockIdx.x * 256;
    int tslab = blockIdx.y * 512;
    float acc = 0.0f;
    for (int t0 = tslab; t0 < tslab + 512; t0 += 32) {
        if (tid < 32) { smax[tid] = g_max[t0 + tid]; sinv[tid] = g_invd[t0 + tid]; }
#pragma unroll
        for (int i = 0; i < 32; i++) {
            int v = tid + i * 256;
            int r = v >> 8, c = v & 255;
            sm[r * 256 + c] = g_logits[(size_t)(t0 + r) * N_SLOT + cb + c];
        }
        __syncthreads();
#pragma unroll
        for (int r = 0; r < 32; r++)
            acc += fexp(sm[r * 256 + tid] - smax[r]) * sinv[r];
        __syncthreads();
    }
    atomicAdd(&g_colsum[cb + tid], acc);
}

// ---------------------------------------------------------------------------
// K5: finalize aux_loss + active_count
//   aux = N * sum_n (colsum[n]/T) * (counts[n]/(tot+1e-9));  N==T==4096
//       = sum_n colsum[n]*counts[n] / (tot + 1e-9)
// ---------------------------------------------------------------------------
__global__ void k_final(float* __restrict__ out, int out_size) {
    __shared__ float r_aux[256];
    __shared__ float r_tot[256];
    __shared__ int   r_act[256];
    int tid = threadIdx.x;
    float aux = 0.0f, tot = 0.0f; int act = 0;
    for (int n = tid; n < N_SLOT; n += 256) {
        int c = g_counts[n];
        tot += (float)c;
        act += (c > 0) ? 1 : 0;
        aux += g_colsum[n] * (float)c;
    }
    r_aux[tid] = aux; r_tot[tid] = tot; r_act[tid] = act;
    __syncthreads();
    for (int s = 128; s > 0; s >>= 1) {
        if (tid < s) {
            r_aux[tid] += r_aux[tid + s];
            r_tot[tid] += r_tot[tid + s];
            r_act[tid] += r_act[tid + s];
        }
        __syncthreads();
    }
    if (tid == 0 && out_size >= (int)((size_t)T_TOK * D_MODEL) + 2) {
        out[out_size - 2] = r_aux[0] / (r_tot[0] + 1e-9f);
        out[out_size - 1] = (float)r_act[0];
    }
}

// ---------------------------------------------------------------------------
// K6: output[t] = sum_k (w_k * (x_t . p_{idx_k})) * p_{idx_k}
// ---------------------------------------------------------------------------
__global__ __launch_bounds__(256) void k_output(const float* __restrict__ x,
                                                const float* __restrict__ pool,
                                                float* __restrict__ out) {
    int t = blockIdx.x;
    int tid = threadIdx.x;
    int lane = tid & 31, warp = tid >> 5;
    __shared__ float sx[D_MODEL];
    __shared__ float swp[MAX_K];
    __shared__ int   sidx[MAX_K];

    reinterpret_cast<float4*>(sx)[tid] =
        reinterpret_cast<const float4*>(x + (size_t)t * D_MODEL)[tid];
    if (tid < MAX_K) sidx[tid] = g_idxbuf[t * MAX_K + tid];
    __syncthreads();

    const float4* x4 = reinterpret_cast<const float4*>(sx);
#pragma unroll
    for (int r = 0; r < 4; r++) {
        int k = warp * 4 + r;
        int pi = sidx[k];
        const float4* p4 = reinterpret_cast<const float4*>(pool + (size_t)pi * D_MODEL);
        float acc = 0.0f;
#pragma unroll
        for (int i = lane; i < 256; i += 32) {
            float4 a = x4[i]; float4 b = p4[i];
            acc += a.x * b.x + a.y * b.y + a.z * b.z + a.w * b.w;
        }
#pragma unroll
        for (int o = 16; o; o >>= 1) acc += __shfl_xor_sync(~0u, acc, o);
        if (lane == 0) swp[k] = g_wbuf[t * MAX_K + k] * acc;
    }
    __syncthreads();

    float4 acc4 = make_float4(0.f, 0.f, 0.f, 0.f);
#pragma unroll
    for (int k = 0; k < MAX_K; k++) {
        float s = swp[k];
        float4 b = reinterpret_cast<const float4*>(pool + (size_t)sidx[k] * D_MODEL)[tid];
        acc4.x += s * b.x; acc4.y += s * b.y;
        acc4.z += s * b.z; acc4.w += s * b.w;
    }
    reinterpret_cast<float4*>(out + (size_t)t * D_MODEL)[tid] = acc4;
}

// ---------------------------------------------------------------------------
// Entry
// ---------------------------------------------------------------------------
extern "C" void kernel_launch(void* const* d_in, const int* in_sizes, int n_in,
                              void* d_out, int out_size) {
    const float* x    = (const float*)d_in[0];   // [4,1024,1024]
    const float* pool = (const float*)d_in[1];   // [4096,1024]
    const float* w    = (const float*)d_in[2];   // [1024,4096]
    float* out = (float*)d_out;

    k_zero<<<16, 256>>>();
    k_gemm<<<dim3(N_SLOT / 128, T_TOK / 128), 256>>>(x, w);
    k_route<<<T_TOK, 256>>>();
    k_colsum<<<dim3(N_SLOT / 256, 8), 256>>>();
    k_final<<<1, 256>>>(out, out_size);
    k_output<<<T_TOK, 256>>>(x, pool, out);
}

// round 3
// speedup vs baseline: 1.0001x; 1.0001x over previous
#include <cuda_runtime.h>
#include <cuda_bf16.h>
#include <stdint.h>

// ---------------------------------------------------------------------------
// Problem constants
// ---------------------------------------------------------------------------
#define T_TOK   4096      // B*S = 4*1024 tokens
#define D_MODEL 1024
#define N_SLOT  4096
#define MAX_K   32
#define MIN_K   8

// ---------------------------------------------------------------------------
// Device-global scratch (allowed; no runtime allocation)
// ---------------------------------------------------------------------------
__device__ float g_logits[(size_t)T_TOK * N_SLOT];   // 64 MB
__device__ float g_max[T_TOK];
__device__ float g_invd[T_TOK];                       // 1/sumexp per token
__device__ float g_colsum[N_SLOT];
__device__ int   g_counts[N_SLOT];
__device__ int   g_idxbuf[T_TOK * MAX_K];
__device__ float g_wbuf[T_TOK * MAX_K];

// ---------------------------------------------------------------------------
// Fast exp (FFMA-only, ~1e-6 rel err) — avoids MUFU throughput wall for the
// ~33M exp evaluations (softmax denom + column means).
// ---------------------------------------------------------------------------
__device__ __forceinline__ float fexp(float x) {
    float y = x * 1.4426950408889634f;          // log2(e)
    y = fmaxf(y, -126.0f);
    float fi = floorf(y);
    float f  = y - fi;                           // f in [0,1)
    // 2^f = exp(f*ln2): Taylor, coeffs ln2^k/k!
    float p = 1.52527338040e-5f;
    p = fmaf(p, f, 1.54035303933e-4f);
    p = fmaf(p, f, 1.33335581464e-3f);
    p = fmaf(p, f, 9.61812910763e-3f);
    p = fmaf(p, f, 5.55041086648e-2f);
    p = fmaf(p, f, 2.40226506959e-1f);
    p = fmaf(p, f, 6.93147180560e-1f);
    p = fmaf(p, f, 1.0f);
    int e = (int)fi;
    return __int_as_float((e + 127) << 23) * p;
}

// monotone float -> uint key (larger float => larger key)
__device__ __forceinline__ unsigned int mono(float f) {
    unsigned int u = __float_as_uint(f);
    return (u & 0x80000000u) ? ~u : (u | 0x80000000u);
}

// ---------------------------------------------------------------------------
// K0: zero accumulators (must run every replay — graph replays N times)
// ---------------------------------------------------------------------------
__global__ void k_zero() {
    int i = blockIdx.x * 256 + threadIdx.x;
    if (i < N_SLOT) { g_colsum[i] = 0.0f; g_counts[i] = 0; }
}

// ---------------------------------------------------------------------------
// K1: logits[T][N] = x[T][D] @ W[D][N]   (fp32 sgemm, 128x128x16 tiles)
// ---------------------------------------------------------------------------
__global__ __launch_bounds__(256) void k_gemm(const float* __restrict__ A,
                                              const float* __restrict__ B) {
    __shared__ float As[16][128];
    __shared__ float Bs[16][128];
    int tid = threadIdx.x;
    int bm = blockIdx.y * 128;
    int bn = blockIdx.x * 128;
    int tm = (tid / 16) * 8;
    int tn = (tid % 16) * 8;
    float acc[8][8];
#pragma unroll
    for (int i = 0; i < 8; i++)
#pragma unroll
        for (int j = 0; j < 8; j++) acc[i][j] = 0.0f;

    for (int k0 = 0; k0 < D_MODEL; k0 += 16) {
        // load A tile 128x16 (transposed into As[k][m])
#pragma unroll
        for (int i = 0; i < 2; i++) {
            int v = tid + i * 256;            // float4 id in [0,512)
            int row = v >> 2;                 // 0..127
            int c4 = (v & 3) * 4;             // 0,4,8,12
            float4 a = *reinterpret_cast<const float4*>(
                &A[(size_t)(bm + row) * D_MODEL + k0 + c4]);
            As[c4 + 0][row] = a.x; As[c4 + 1][row] = a.y;
            As[c4 + 2][row] = a.z; As[c4 + 3][row] = a.w;
        }
        // load B tile 16x128
#pragma unroll
        for (int i = 0; i < 2; i++) {
            int v = tid + i * 256;
            int row = v >> 5;                 // 0..15
            int c4 = (v & 31) * 4;
            *reinterpret_cast<float4*>(&Bs[row][c4]) =
                *reinterpret_cast<const float4*>(
                    &B[(size_t)(k0 + row) * N_SLOT + bn + c4]);
        }
        __syncthreads();
#pragma unroll
        for (int k = 0; k < 16; k++) {
            float ar[8], br[8];
#pragma unroll
            for (int i = 0; i < 8; i++) ar[i] = As[k][tm + i];
#pragma unroll
            for (int j = 0; j < 8; j++) br[j] = Bs[k][tn + j];
#pragma unroll
            for (int i = 0; i < 8; i++)
#pragma unroll
                for (int j = 0; j < 8; j++)
                    acc[i][j] = fmaf(ar[i], br[j], acc[i][j]);
        }
        __syncthreads();
    }
#pragma unroll
    for (int i = 0; i < 8; i++) {
        float* crow = &g_logits[(size_t)(bm + tm + i) * N_SLOT + bn + tn];
        *reinterpret_cast<float4*>(crow) =
            make_float4(acc[i][0], acc[i][1], acc[i][2], acc[i][3]);
        *reinterpret_cast<float4*>(crow + 4) =
            make_float4(acc[i][4], acc[i][5], acc[i][6], acc[i][7]);
    }
}

// ---------------------------------------------------------------------------
// K2: per-token softmax stats + exact top-32 (radix select + warp bitonic),
//     keep mask, weights, scatter counts.
// ---------------------------------------------------------------------------
__global__ __launch_bounds__(256) void k_route() {
    int t = blockIdx.x;
    int tid = threadIdx.x;
    const float* row = g_logits + (size_t)t * N_SLOT;

    __shared__ float sv[N_SLOT];
    __shared__ unsigned int hist[256];
    __shared__ float red[8];
    __shared__ unsigned int s_prefix;
    __shared__ int s_want;
    __shared__ int s_cnt, s_eqcnt;
    __shared__ int sel[32];
    __shared__ int eqlist[64];
    __shared__ float s_max, s_sum;

    // load row + local max
    float lmax = -3.4e38f;
    float vals[16];
#pragma unroll
    for (int j = 0; j < 16; j++) {
        int i = tid + j * 256;
        float v = row[i];
        sv[i] = v;
        vals[j] = v;
        lmax = fmaxf(lmax, v);
    }
    // block max
#pragma unroll
    for (int o = 16; o; o >>= 1) lmax = fmaxf(lmax, __shfl_xor_sync(~0u, lmax, o));
    if ((tid & 31) == 0) red[tid >> 5] = lmax;
    __syncthreads();
    if (tid == 0) {
        float m = red[0];
#pragma unroll
        for (int w = 1; w < 8; w++) m = fmaxf(m, red[w]);
        s_max = m;
    }
    __syncthreads();
    float m = s_max;

    // block sumexp
    float lsum = 0.0f;
#pragma unroll
    for (int j = 0; j < 16; j++) lsum += fexp(vals[j] - m);
#pragma unroll
    for (int o = 16; o; o >>= 1) lsum += __shfl_xor_sync(~0u, lsum, o);
    if ((tid & 31) == 0) red[tid >> 5] = lsum;
    __syncthreads();
    if (tid == 0) {
        float s = 0.0f;
#pragma unroll
        for (int w = 0; w < 8; w++) s += red[w];
        s_sum = s;
    }
    __syncthreads();

    // ---- radix select for 32nd largest key ----
    unsigned int prefmask = 0u, prefix = 0u;
    int want = 32;
    for (int shift = 24; shift >= 0; shift -= 8) {
        hist[tid] = 0u;
        __syncthreads();
#pragma unroll
        for (int j = 0; j < 16; j++) {
            unsigned int kk = mono(vals[j]);
            if ((kk & prefmask) == prefix)
                atomicAdd(&hist[(kk >> shift) & 255u], 1u);
        }
        __syncthreads();
        if (tid == 0) {
            int cum = 0, b = 255;
            for (; b >= 0; b--) { cum += (int)hist[b]; if (cum >= want) break; }
            s_prefix = prefix | ((unsigned int)b << shift);
            s_want = want - (cum - (int)hist[b]);
        }
        __syncthreads();
        prefix = s_prefix;
        want = s_want;
        prefmask |= 0xFFu << shift;
        __syncthreads();
    }

    // ---- compaction ----
    if (tid == 0) { s_cnt = 0; s_eqcnt = 0; }
    __syncthreads();
#pragma unroll
    for (int j = 0; j < 16; j++) {
        int i = tid + j * 256;
        unsigned int kk = mono(vals[j]);
        if (kk > prefix) {
            int p = atomicAdd(&s_cnt, 1);
            if (p < 32) sel[p] = i;
        } else if (kk == prefix) {
            int p = atomicAdd(&s_eqcnt, 1);
            if (p < 64) eqlist[p] = i;
        }
    }
    __syncthreads();
    if (tid == 0) {
        // ties: lowest indices first (jax tie-break)
        int n = s_eqcnt < 64 ? s_eqcnt : 64;
        for (int a = 1; a < n; a++) {
            int key = eqlist[a]; int b = a - 1;
            while (b >= 0 && eqlist[b] > key) { eqlist[b + 1] = eqlist[b]; b--; }
            eqlist[b + 1] = key;
        }
        int base = s_cnt;
        for (int r = 0; r < want && r < n && base + r < 32; r++)
            sel[base + r] = eqlist[r];
    }
    __syncthreads();

    // ---- warp 0: bitonic sort 32 selected (value desc, index asc) ----
    if (tid < 32) {
        int idx = sel[tid];
        float val = sv[idx];
        unsigned long long key =
            ((unsigned long long)mono(val) << 32) |
            (unsigned long long)(0xFFFFFFFFu - (unsigned int)idx);
#pragma unroll
        for (int k = 2; k <= 32; k <<= 1) {
#pragma unroll
            for (int j = k >> 1; j > 0; j >>= 1) {
                unsigned long long o = __shfl_xor_sync(0xFFFFFFFFu, key, j);
                bool up = ((tid & k) == 0);
                bool takeMin = (((tid & j) == 0) == up);
                unsigned long long mn = key < o ? key : o;
                unsigned long long mx = key < o ? o : key;
                key = takeMin ? mn : mx;
            }
        }
        int rank = 31 - tid;  // ascending sort -> rank 0 at lane 31
        unsigned int myidx = 0xFFFFFFFFu - (unsigned int)(key & 0xFFFFFFFFu);
        float v = sv[myidx];
        float prob = fexp(v - s_max) * (1.0f / s_sum);
        bool keep = (rank < MIN_K) || (prob > (1.0f / (float)N_SLOT));
        float masked = keep ? prob : 0.0f;
        float ws = masked;
#pragma unroll
        for (int o = 16; o; o >>= 1) ws += __shfl_xor_sync(~0u, ws, o);
        float w = masked / (ws + 1e-9f);
        g_idxbuf[t * MAX_K + rank] = (int)myidx;
        g_wbuf[t * MAX_K + rank] = w;
        if (keep) atomicAdd(&g_counts[myidx], 1);
        if (tid == 0) { g_max[t] = s_max; g_invd[t] = 1.0f / s_sum; }
    }
}

// ---------------------------------------------------------------------------
// K3: column sums of softmax probs (for mean_probs / aux loss)
//     grid (N/256, 8); each block: 256 cols x 512 tokens
// ---------------------------------------------------------------------------
__global__ __launch_bounds__(256) void k_colsum() {
    __shared__ float sm[32 * 256];
    __shared__ float smax[32], sinv[32];
    int tid = threadIdx.x;
    int cb = blockIdx.x * 256;
    int tslab = blockIdx.y * 512;
    float acc = 0.0f;
    for (int t0 = tslab; t0 < tslab + 512; t0 += 32) {
        if (tid < 32) { smax[tid] = g_max[t0 + tid]; sinv[tid] = g_invd[t0 + tid]; }
#pragma unroll
        for (int i = 0; i < 32; i++) {
            int v = tid + i * 256;
            int r = v >> 8, c = v & 255;
            sm[r * 256 + c] = g_logits[(size_t)(t0 + r) * N_SLOT + cb + c];
        }
        __syncthreads();
#pragma unroll
        for (int r = 0; r < 32; r++)
            acc += fexp(sm[r * 256 + tid] - smax[r]) * sinv[r];
        __syncthreads();
    }
    atomicAdd(&g_colsum[cb + tid], acc);
}

// ---------------------------------------------------------------------------
// K5: finalize aux_loss + active_count
//   aux = N * sum_n (colsum[n]/T) * (counts[n]/(tot+1e-9));  N==T==4096
//       = sum_n colsum[n]*counts[n] / (tot + 1e-9)
// ---------------------------------------------------------------------------
__global__ void k_final(float* __restrict__ out, int out_size) {
    __shared__ float r_aux[256];
    __shared__ float r_tot[256];
    __shared__ int   r_act[256];
    int tid = threadIdx.x;
    float aux = 0.0f, tot = 0.0f; int act = 0;
    for (int n = tid; n < N_SLOT; n += 256) {
        int c = g_counts[n];
        tot += (float)c;
        act += (c > 0) ? 1 : 0;
        aux += g_colsum[n] * (float)c;
    }
    r_aux[tid] = aux; r_tot[tid] = tot; r_act[tid] = act;
    __syncthreads();
    for (int s = 128; s > 0; s >>= 1) {
        if (tid < s) {
            r_aux[tid] += r_aux[tid + s];
            r_tot[tid] += r_tot[tid + s];
            r_act[tid] += r_act[tid + s];
        }
        __syncthreads();
    }
    if (tid == 0 && out_size >= (int)((size_t)T_TOK * D_MODEL) + 2) {
        out[out_size - 2] = r_aux[0] / (r_tot[0] + 1e-9f);
        out[out_size - 1] = (float)r_act[0];
    }
}

// ---------------------------------------------------------------------------
// K6: output[t] = sum_k (w_k * (x_t . p_{idx_k})) * p_{idx_k}
// ---------------------------------------------------------------------------
__global__ __launch_bounds__(256) void k_output(const float* __restrict__ x,
                                                const float* __restrict__ pool,
                                                float* __restrict__ out) {
    int t = blockIdx.x;
    int tid = threadIdx.x;
    int lane = tid & 31, warp = tid >> 5;
    __shared__ float sx[D_MODEL];
    __shared__ float swp[MAX_K];
    __shared__ int   sidx[MAX_K];

    reinterpret_cast<float4*>(sx)[tid] =
        reinterpret_cast<const float4*>(x + (size_t)t * D_MODEL)[tid];
    if (tid < MAX_K) sidx[tid] = g_idxbuf[t * MAX_K + tid];
    __syncthreads();

    const float4* x4 = reinterpret_cast<const float4*>(sx);
#pragma unroll
    for (int r = 0; r < 4; r++) {
        int k = warp * 4 + r;
        int pi = sidx[k];
        const float4* p4 = reinterpret_cast<const float4*>(pool + (size_t)pi * D_MODEL);
        float acc = 0.0f;
#pragma unroll
        for (int i = lane; i < 256; i += 32) {
            float4 a = x4[i]; float4 b = p4[i];
            acc += a.x * b.x + a.y * b.y + a.z * b.z + a.w * b.w;
        }
#pragma unroll
        for (int o = 16; o; o >>= 1) acc += __shfl_xor_sync(~0u, acc, o);
        if (lane == 0) swp[k] = g_wbuf[t * MAX_K + k] * acc;
    }
    __syncthreads();

    float4 acc4 = make_float4(0.f, 0.f, 0.f, 0.f);
#pragma unroll
    for (int k = 0; k < MAX_K; k++) {
        float s = swp[k];
        float4 b = reinterpret_cast<const float4*>(pool + (size_t)sidx[k] * D_MODEL)[tid];
        acc4.x += s * b.x; acc4.y += s * b.y;
        acc4.z += s * b.z; acc4.w += s * b.w;
    }
    reinterpret_cast<float4*>(out + (size_t)t * D_MODEL)[tid] = acc4;
}

// ---------------------------------------------------------------------------
// Entry
// ---------------------------------------------------------------------------
extern "C" void kernel_launch(void* const* d_in, const int* in_sizes, int n_in,
                              void* d_out, int out_size) {
    const float* x    = (const float*)d_in[0];   // [4,1024,1024]
    const float* pool = (const float*)d_in[1];   // [4096,1024]
    const float* w    = (const float*)d_in[2];   // [1024,4096]
    float* out = (float*)d_out;

    k_zero<<<16, 256>>>();
    k_gemm<<<dim3(N_SLOT / 128, T_TOK / 128), 256>>>(x, w);
    k_route<<<T_TOK, 256>>>();
    k_colsum<<<dim3(N_SLOT / 256, 8), 256>>>();
    k_final<<<1, 256>>>(out, out_size);
    k_output<<<T_TOK, 256>>>(x, pool, out);
}